// round 2
// baseline (speedup 1.0000x reference)
#include <cuda_runtime.h>
#include <cuda_fp16.h>
#include <cstdint>

// Problem constants
#define NB 1024
#define NN 256
#define FF 63
#define DD 64

// smem byte offsets
#define OFF_V    0          // half Vhi[256][72]        36864 B
#define OFF_WHI  36864      // half Whi[64][136]        17408 B
#define OFF_WLO  54272      // half Wlo[64][136]        17408 B
#define OFF_P    71680      // float P[256][136]       139264 B (cols 0-63 Hrel, 64-127 Hroot->x)
#define OFF_B1   210944     // float[64]
#define OFF_R0J  211200     // int[64]
#define OFF_R0V  211456     // float[64]
#define OFF_SA   211712     // float[64]
#define OFF_SB   211968     // float[64]
#define OFF_CNT  212224     // int
#define SMEM_BYTES 212240
// W2s reuses OFF_V region after the MMA phase (8192 floats = 32768 B <= 36864)

__device__ __forceinline__ uint32_t smem_u32(const void* p) {
    return (uint32_t)__cvta_generic_to_shared(p);
}

__device__ __forceinline__ void ldsm_x4(uint32_t addr, uint32_t& r0, uint32_t& r1,
                                        uint32_t& r2, uint32_t& r3) {
    asm volatile("ldmatrix.sync.aligned.m8n8.x4.shared.b16 {%0,%1,%2,%3}, [%4];"
                 : "=r"(r0), "=r"(r1), "=r"(r2), "=r"(r3) : "r"(addr));
}

__device__ __forceinline__ void ldsm_x4t(uint32_t addr, uint32_t& r0, uint32_t& r1,
                                         uint32_t& r2, uint32_t& r3) {
    asm volatile("ldmatrix.sync.aligned.m8n8.x4.trans.shared.b16 {%0,%1,%2,%3}, [%4];"
                 : "=r"(r0), "=r"(r1), "=r"(r2), "=r"(r3) : "r"(addr));
}

__device__ __forceinline__ void mma16816(float* d, uint32_t a0, uint32_t a1,
                                         uint32_t a2, uint32_t a3,
                                         uint32_t b0, uint32_t b1) {
    asm volatile(
        "mma.sync.aligned.m16n8k16.row.col.f32.f16.f16.f32 "
        "{%0,%1,%2,%3}, {%4,%5,%6,%7}, {%8,%9}, {%0,%1,%2,%3};"
        : "+f"(d[0]), "+f"(d[1]), "+f"(d[2]), "+f"(d[3])
        : "r"(a0), "r"(a1), "r"(a2), "r"(a3), "r"(b0), "r"(b1));
}

__global__ void __launch_bounds__(256, 1) gnn_fused_kernel(
    const float* __restrict__ adj, const float* __restrict__ vec,
    const float* __restrict__ w1_rel, const float* __restrict__ w1_root,
    const float* __restrict__ b1,
    const float* __restrict__ w2_rel, const float* __restrict__ w2_root,
    const float* __restrict__ b2,
    const float* __restrict__ wf, const float* __restrict__ bf,
    float* __restrict__ out)
{
    extern __shared__ char smem[];
    __half* Vh   = (__half*)(smem + OFF_V);
    __half* Whi  = (__half*)(smem + OFF_WHI);
    __half* Wlo  = (__half*)(smem + OFF_WLO);
    float*  Pf   = (float*)(smem + OFF_P);
    float*  B1s  = (float*)(smem + OFF_B1);
    int*    R0J  = (int*)(smem + OFF_R0J);
    float*  R0V  = (float*)(smem + OFF_R0V);
    float*  SA   = (float*)(smem + OFF_SA);
    float*  SB   = (float*)(smem + OFF_SB);
    int*    CNT  = (int*)(smem + OFF_CNT);
    float*  W2s  = (float*)(smem + OFF_V);   // reused after MMA

    const int tid  = threadIdx.x;
    const int lane = tid & 31;
    const int wid  = tid >> 5;
    const int b    = blockIdx.x;

    // ---------------- Phase A: load vec (fp16) + split weights ----------------
    {
        const float* vsrc = vec + (size_t)b * (NN * FF);
        for (int idx = tid; idx < NN * FF; idx += 256) {
            int r = idx / FF, c = idx - r * FF;
            Vh[r * 72 + c] = __float2half(vsrc[idx]);
        }
        if (tid < NN) Vh[tid * 72 + 63] = __float2half(0.0f);  // zero pad col 63

        for (int idx = tid; idx < FF * DD; idx += 256) {
            int k = idx >> 6, n = idx & 63;
            float wr = w1_rel[idx], wt = w1_root[idx];
            __half hr = __float2half(wr), ht = __float2half(wt);
            Whi[k * 136 + n]      = hr;
            Wlo[k * 136 + n]      = __float2half(wr - __half2float(hr));
            Whi[k * 136 + 64 + n] = ht;
            Wlo[k * 136 + 64 + n] = __float2half(wt - __half2float(ht));
        }
        if (tid < 128) {  // zero pad k=63 row
            Whi[63 * 136 + tid] = __float2half(0.0f);
            Wlo[63 * 136 + tid] = __float2half(0.0f);
        }
        if (tid < 64) B1s[tid] = b1[tid];
    }
    __syncthreads();

    // ---------------- Phase A2: P = Vh @ [Whi|Wlo adjusted] via mma.sync -------
    {
        const int row16 = lane & 15;
        const int half8 = (lane >> 4) << 3;  // 0 or 8
#pragma unroll
        for (int mt = 0; mt < 2; ++mt) {
            const int mb = wid * 32 + mt * 16;
            float acc[16][4];
#pragma unroll
            for (int nt = 0; nt < 16; ++nt)
#pragma unroll
                for (int q = 0; q < 4; ++q) acc[nt][q] = 0.0f;

#pragma unroll
            for (int kt = 0; kt < 4; ++kt) {
                uint32_t a0, a1, a2, a3;
                uint32_t aaddr = smem_u32(&Vh[(mb + row16) * 72 + kt * 16 + half8]);
                ldsm_x4(aaddr, a0, a1, a2, a3);
#pragma unroll
                for (int pass = 0; pass < 2; ++pass) {
                    const __half* Wb = pass ? Wlo : Whi;
#pragma unroll
                    for (int nt2 = 0; nt2 < 8; ++nt2) {
                        uint32_t b0, b1r, b2r, b3r;
                        uint32_t baddr = smem_u32(
                            &Wb[(kt * 16 + row16) * 136 + nt2 * 16 + half8]);
                        ldsm_x4t(baddr, b0, b1r, b2r, b3r);
                        mma16816(acc[2 * nt2],     a0, a1, a2, a3, b0, b1r);
                        mma16816(acc[2 * nt2 + 1], a0, a1, a2, a3, b2r, b3r);
                    }
                }
            }
            // store accumulators to P (fp32)
            const int r0 = mb + (lane >> 2);
            const int c0 = (lane & 3) * 2;
#pragma unroll
            for (int nt = 0; nt < 16; ++nt) {
                *(float2*)&Pf[r0 * 136 + nt * 8 + c0] =
                    make_float2(acc[nt][0], acc[nt][1]);
                *(float2*)&Pf[(r0 + 8) * 136 + nt * 8 + c0] =
                    make_float2(acc[nt][2], acc[nt][3]);
            }
        }
    }
    __syncthreads();

    // ---------------- Phase B: stream adj, sparse-aggregate Hrel ----------------
    {
        // stage w2 weights into reused smem (read in Phase D)
        const float4* wr4 = (const float4*)w2_rel;
        const float4* wt4 = (const float4*)w2_root;
        for (int p = tid; p < 1024; p += 256) {
            ((float4*)W2s)[p]        = wr4[p];
            ((float4*)(W2s + 4096))[p] = wt4[p];
        }

        const float4* ab = (const float4*)(adj + (size_t)b * (NN * NN));
        int i = wid * 32;
        float4 va = ab[i * 64 + lane];
        float4 vb = ab[i * 64 + 32 + lane];
        int cnt0 = 0;

        for (int r = 0; r < 32; ++r) {
            float4 na, nb;
            if (r < 31) {
                na = ab[(i + 1) * 64 + lane];
                nb = ab[(i + 1) * 64 + 32 + lane];
            }
            float accx = 0.0f, accy = 0.0f;
            const int is0 = (i == 0);
            float vals[8] = {va.x, va.y, va.z, va.w, vb.x, vb.y, vb.z, vb.w};
#pragma unroll
            for (int e = 0; e < 8; ++e) {
                float v = vals[e];
                unsigned m = __ballot_sync(0xffffffffu, v != 0.0f);
                while (m) {
                    int l = __ffs(m) - 1;
                    m &= m - 1;
                    float vv = __shfl_sync(0xffffffffu, v, l);
                    int jj = (e < 4) ? (l * 4 + e) : (128 + l * 4 + (e - 4));
                    float2 h = *(const float2*)&Pf[jj * 136 + 2 * lane];
                    accx = fmaf(vv, h.x, accx);
                    accy = fmaf(vv, h.y, accy);
                    if (is0) {  // capture row-0 nz list for layer 2
                        if (lane == 0 && cnt0 < 64) { R0J[cnt0] = jj; R0V[cnt0] = vv; }
                        cnt0++;
                    }
                }
            }
            // x[i] = relu(agg + Hroot + b1), stored in P cols 64..127
            float hr0 = Pf[i * 136 + 64 + 2 * lane]     + B1s[2 * lane];
            float hr1 = Pf[i * 136 + 64 + 2 * lane + 1] + B1s[2 * lane + 1];
            Pf[i * 136 + 64 + 2 * lane]     = fmaxf(accx + hr0, 0.0f);
            Pf[i * 136 + 64 + 2 * lane + 1] = fmaxf(accy + hr1, 0.0f);
            if (is0 && lane == 0) *CNT = (cnt0 < 64) ? cnt0 : 64;
            va = na; vb = nb; ++i;
        }
    }
    __syncthreads();

    // ---------------- Phase D: layer-2 readout at node 0 (exact fp32) ----------
    if (tid < 64) {
        int cnt = *CNT;
        float s = 0.0f;
        for (int q = 0; q < cnt; ++q)
            s = fmaf(R0V[q], Pf[R0J[q] * 136 + 64 + tid], s);
        SA[tid] = s;  // t = adj0 @ x
    }
    __syncthreads();
    if (tid < 64) {
        float acc = b2[tid];
#pragma unroll 8
        for (int d = 0; d < 64; ++d)
            acc += SA[d] * W2s[d * 64 + tid] + Pf[64 + d] * W2s[4096 + d * 64 + tid];
        float y = fmaxf(acc, 0.0f);
        SB[tid] = y + Pf[64 + tid];  // x0 + y0
    }
    __syncthreads();
    if (tid < 2) {
        float s = bf[tid];
#pragma unroll 16
        for (int d = 0; d < 64; ++d) s = fmaf(SB[d], wf[d * 2 + tid], s);
        out[(size_t)b * 2 + tid] = s;
    }
}

extern "C" void kernel_launch(void* const* d_in, const int* in_sizes, int n_in,
                              void* d_out, int out_size) {
    const float* adj     = (const float*)d_in[0];
    const float* vec     = (const float*)d_in[1];
    const float* w1_rel  = (const float*)d_in[2];
    const float* w1_root = (const float*)d_in[3];
    const float* b1      = (const float*)d_in[4];
    const float* w2_rel  = (const float*)d_in[5];
    const float* w2_root = (const float*)d_in[6];
    const float* b2      = (const float*)d_in[7];
    const float* wf      = (const float*)d_in[8];
    const float* bf      = (const float*)d_in[9];
    float* out = (float*)d_out;

    cudaFuncSetAttribute(gnn_fused_kernel,
                         cudaFuncAttributeMaxDynamicSharedMemorySize, SMEM_BYTES);
    gnn_fused_kernel<<<NB, 256, SMEM_BYTES>>>(
        adj, vec, w1_rel, w1_root, b1, w2_rel, w2_root, b2, wf, bf, out);
}

// round 3
// speedup vs baseline: 1.7295x; 1.7295x over previous
#include <cuda_runtime.h>
#include <cuda_fp16.h>
#include <cstdint>

// Problem constants
#define NB 1024
#define NN 256
#define FF 63
#define DD 64

// smem byte offsets
#define OFF_V    0          // half Vh[256][72]         36864 B  (reused as W2s: 32768 B)
#define OFF_WHI  36864      // half Whi[64][136]        17408 B
#define OFF_WLO  54272      // half Wlo[64][136]        17408 B
#define OFF_P    71680      // float P[256][136]       139264 B (cols 0-63 Hrel, 64-127 Hroot->x)
#define OFF_B1   210944     // float[64]
#define OFF_A0   211200     // float[256] adj row 0
#define OFF_PART 212224     // float[256]
#define OFF_SA   213248     // float[64]
#define OFF_SB   213504     // float[64]
#define SMEM_BYTES 213760

__device__ __forceinline__ uint32_t smem_u32(const void* p) {
    return (uint32_t)__cvta_generic_to_shared(p);
}

__device__ __forceinline__ void ldsm_x4(uint32_t addr, uint32_t& r0, uint32_t& r1,
                                        uint32_t& r2, uint32_t& r3) {
    asm volatile("ldmatrix.sync.aligned.m8n8.x4.shared.b16 {%0,%1,%2,%3}, [%4];"
                 : "=r"(r0), "=r"(r1), "=r"(r2), "=r"(r3) : "r"(addr));
}

__device__ __forceinline__ void ldsm_x4t(uint32_t addr, uint32_t& r0, uint32_t& r1,
                                         uint32_t& r2, uint32_t& r3) {
    asm volatile("ldmatrix.sync.aligned.m8n8.x4.trans.shared.b16 {%0,%1,%2,%3}, [%4];"
                 : "=r"(r0), "=r"(r1), "=r"(r2), "=r"(r3) : "r"(addr));
}

__device__ __forceinline__ void mma16816(float* d, uint32_t a0, uint32_t a1,
                                         uint32_t a2, uint32_t a3,
                                         uint32_t b0, uint32_t b1) {
    asm volatile(
        "mma.sync.aligned.m16n8k16.row.col.f32.f16.f16.f32 "
        "{%0,%1,%2,%3}, {%4,%5,%6,%7}, {%8,%9}, {%0,%1,%2,%3};"
        : "+f"(d[0]), "+f"(d[1]), "+f"(d[2]), "+f"(d[3])
        : "r"(a0), "r"(a1), "r"(a2), "r"(a3), "r"(b0), "r"(b1));
}

__global__ void __launch_bounds__(512, 1) gnn_fused_kernel(
    const float* __restrict__ adj, const float* __restrict__ vec,
    const float* __restrict__ w1_rel, const float* __restrict__ w1_root,
    const float* __restrict__ b1,
    const float* __restrict__ w2_rel, const float* __restrict__ w2_root,
    const float* __restrict__ b2,
    const float* __restrict__ wf, const float* __restrict__ bf,
    float* __restrict__ out)
{
    extern __shared__ char smem[];
    __half* Vh   = (__half*)(smem + OFF_V);
    __half* Whi  = (__half*)(smem + OFF_WHI);
    __half* Wlo  = (__half*)(smem + OFF_WLO);
    float*  Pf   = (float*)(smem + OFF_P);
    float*  B1s  = (float*)(smem + OFF_B1);
    float*  A0s  = (float*)(smem + OFF_A0);
    float*  PART = (float*)(smem + OFF_PART);
    float*  SA   = (float*)(smem + OFF_SA);
    float*  SB   = (float*)(smem + OFF_SB);
    float*  W2s  = (float*)(smem + OFF_V);   // reused after MMA phase

    const int tid  = threadIdx.x;
    const int lane = tid & 31;
    const int wid  = tid >> 5;
    const int b    = blockIdx.x;

    // ---------------- Phase A: load vec (fp16) + split weights ----------------
    {
        const float* vsrc = vec + (size_t)b * (NN * FF);
        for (int idx = tid; idx < NN * FF; idx += 512) {
            int r = idx / FF, c = idx - r * FF;
            Vh[r * 72 + c] = __float2half(vsrc[idx]);
        }
        if (tid < NN) Vh[tid * 72 + 63] = __float2half(0.0f);  // zero pad col 63

        for (int idx = tid; idx < FF * DD; idx += 512) {
            int k = idx >> 6, n = idx & 63;
            float wr = w1_rel[idx], wt = w1_root[idx];
            __half hr = __float2half(wr), ht = __float2half(wt);
            Whi[k * 136 + n]      = hr;
            Wlo[k * 136 + n]      = __float2half(wr - __half2float(hr));
            Whi[k * 136 + 64 + n] = ht;
            Wlo[k * 136 + 64 + n] = __float2half(wt - __half2float(ht));
        }
        if (tid < 128) {  // zero pad k=63 row
            Whi[63 * 136 + tid] = __float2half(0.0f);
            Wlo[63 * 136 + tid] = __float2half(0.0f);
        }
        if (tid < 64) B1s[tid] = b1[tid];
    }
    __syncthreads();

    // ------- Phase A2: P = Vh @ [Whi + Wlo] via mma.sync, 16 warps x 16 rows ---
    {
        const int row16 = lane & 15;
        const int half8 = (lane >> 4) << 3;  // 0 or 8
        const int mb = wid * 16;
#pragma unroll
        for (int nh = 0; nh < 2; ++nh) {     // n-half: cols nh*64 .. nh*64+63
            float acc[8][4];
#pragma unroll
            for (int q = 0; q < 8; ++q)
#pragma unroll
                for (int t = 0; t < 4; ++t) acc[q][t] = 0.0f;

#pragma unroll
            for (int kt = 0; kt < 4; ++kt) {
                uint32_t a0, a1, a2, a3;
                uint32_t aaddr = smem_u32(&Vh[(mb + row16) * 72 + kt * 16 + half8]);
                ldsm_x4(aaddr, a0, a1, a2, a3);
#pragma unroll
                for (int pass = 0; pass < 2; ++pass) {
                    const __half* Wb = pass ? Wlo : Whi;
#pragma unroll
                    for (int nt = 0; nt < 4; ++nt) {
                        uint32_t b0, b1r, b2r, b3r;
                        uint32_t baddr = smem_u32(
                            &Wb[(kt * 16 + row16) * 136 + nh * 64 + nt * 16 + half8]);
                        ldsm_x4t(baddr, b0, b1r, b2r, b3r);
                        mma16816(acc[2 * nt],     a0, a1, a2, a3, b0, b1r);
                        mma16816(acc[2 * nt + 1], a0, a1, a2, a3, b2r, b3r);
                    }
                }
            }
            const int r0 = mb + (lane >> 2);
            const int c0 = (lane & 3) * 2;
#pragma unroll
            for (int q = 0; q < 8; ++q) {
                *(float2*)&Pf[r0 * 136 + nh * 64 + q * 8 + c0] =
                    make_float2(acc[q][0], acc[q][1]);
                *(float2*)&Pf[(r0 + 8) * 136 + nh * 64 + q * 8 + c0] =
                    make_float2(acc[q][2], acc[q][3]);
            }
        }
    }
    __syncthreads();

    // ---------------- Phase B: stream adj, sparse-aggregate Hrel ----------------
    {
        // stage w2 weights + adj row 0 (Vh region is dead now)
        const float4* wr4 = (const float4*)w2_rel;
        const float4* wt4 = (const float4*)w2_root;
        for (int p = tid; p < 1024; p += 512) {
            ((float4*)W2s)[p]          = wr4[p];
            ((float4*)(W2s + 4096))[p] = wt4[p];
        }
        const float* arow0 = adj + (size_t)b * (NN * NN);
        if (tid < NN) A0s[tid] = arow0[tid];

        const float4* ab = (const float4*)(adj + (size_t)b * (NN * NN));
        const int base = wid * 16;

        // prefetch rows base, base+1 (distance-2 double buffer)
        float4 e0a = ab[(base + 0) * 64 + lane];
        float4 e0b = ab[(base + 0) * 64 + 32 + lane];
        float4 e1a = ab[(base + 1) * 64 + lane];
        float4 e1b = ab[(base + 1) * 64 + 32 + lane];

#pragma unroll 2
        for (int r = 0; r < 16; ++r) {
            const int i = base + r;
            float4 va = (r & 1) ? e1a : e0a;
            float4 vb = (r & 1) ? e1b : e0b;
            // prefetch row r+2 into the slot just freed
            if (r < 14) {
                const int ip = i + 2;
                float4 pa = ab[ip * 64 + lane];
                float4 pb = ab[ip * 64 + 32 + lane];
                if (r & 1) { e1a = pa; e1b = pb; }
                else       { e0a = pa; e0b = pb; }
            }

            float accx = 0.0f, accy = 0.0f;
            float vals[8] = {va.x, va.y, va.z, va.w, vb.x, vb.y, vb.z, vb.w};
#pragma unroll
            for (int e = 0; e < 8; ++e) {
                float v = vals[e];
                unsigned m = __ballot_sync(0xffffffffu, v != 0.0f);
                while (m) {
                    int l = __ffs(m) - 1;
                    m &= m - 1;
                    float vv = __shfl_sync(0xffffffffu, v, l);
                    int jj = (e < 4) ? (l * 4 + e) : (128 + l * 4 + (e - 4));
                    float2 h = *(const float2*)&Pf[jj * 136 + 2 * lane];
                    accx = fmaf(vv, h.x, accx);
                    accy = fmaf(vv, h.y, accy);
                }
            }
            // x[i] = relu(agg + Hroot + b1), stored in P cols 64..127
            float hr0 = Pf[i * 136 + 64 + 2 * lane]     + B1s[2 * lane];
            float hr1 = Pf[i * 136 + 64 + 2 * lane + 1] + B1s[2 * lane + 1];
            Pf[i * 136 + 64 + 2 * lane]     = fmaxf(accx + hr0, 0.0f);
            Pf[i * 136 + 64 + 2 * lane + 1] = fmaxf(accy + hr1, 0.0f);
        }
    }
    __syncthreads();

    // ---------------- Phase D: layer-2 readout at node 0 (exact fp32) ----------
    // SA = adj[0,:] @ x  (dense, 4-way split reduction)
    if (tid < 256) {
        const int g = tid >> 6, c = tid & 63;
        float s = 0.0f;
#pragma unroll 8
        for (int q = 0; q < 64; ++q) {
            const int j = g * 64 + q;
            s = fmaf(A0s[j], Pf[j * 136 + 64 + c], s);
        }
        PART[tid] = s;
    }
    __syncthreads();
    if (tid < 64)
        SA[tid] = PART[tid] + PART[64 + tid] + PART[128 + tid] + PART[192 + tid];
    __syncthreads();
    if (tid < 64) {
        float acc = b2[tid];
#pragma unroll 8
        for (int d = 0; d < 64; ++d)
            acc += SA[d] * W2s[d * 64 + tid] + Pf[64 + d] * W2s[4096 + d * 64 + tid];
        float y = fmaxf(acc, 0.0f);
        SB[tid] = y + Pf[64 + tid];  // x0 + y0
    }
    __syncthreads();
    if (tid < 2) {
        float s = bf[tid];
#pragma unroll 16
        for (int d = 0; d < 64; ++d) s = fmaf(SB[d], wf[d * 2 + tid], s);
        out[(size_t)b * 2 + tid] = s;
    }
}

extern "C" void kernel_launch(void* const* d_in, const int* in_sizes, int n_in,
                              void* d_out, int out_size) {
    const float* adj     = (const float*)d_in[0];
    const float* vec     = (const float*)d_in[1];
    const float* w1_rel  = (const float*)d_in[2];
    const float* w1_root = (const float*)d_in[3];
    const float* b1      = (const float*)d_in[4];
    const float* w2_rel  = (const float*)d_in[5];
    const float* w2_root = (const float*)d_in[6];
    const float* b2      = (const float*)d_in[7];
    const float* wf      = (const float*)d_in[8];
    const float* bf      = (const float*)d_in[9];
    float* out = (float*)d_out;

    cudaFuncSetAttribute(gnn_fused_kernel,
                         cudaFuncAttributeMaxDynamicSharedMemorySize, SMEM_BYTES);
    gnn_fused_kernel<<<NB, 512, SMEM_BYTES>>>(
        adj, vec, w1_rel, w1_root, b1, w2_rel, w2_root, b2, wf, bf, out);
}

// round 4
// speedup vs baseline: 1.8022x; 1.0421x over previous
#include <cuda_runtime.h>
#include <cuda_fp16.h>
#include <cstdint>

// Problem constants
#define NB 1024
#define NN 256
#define FF 63
#define DD 64

// smem byte offsets
#define OFF_V    0          // half Vh[256][72]         36864 B  (reused as W2s: 32768 B)
#define OFF_WHI  36864      // half Whi[64][136]        17408 B
#define OFF_WLO  54272      // half Wlo[64][136]        17408 B
#define OFF_P    71680      // float P[256][136]       139264 B (cols 0-63 Hrel, 64-127 Hroot->x)
#define OFF_B1   210944     // float[64]
#define OFF_A0   211200     // float[256] adj row 0
#define OFF_PART 212224     // float[256]
#define OFF_SA   213248     // float[64]
#define OFF_SB   213504     // float[64]
#define SMEM_BYTES 213760

__device__ __forceinline__ uint32_t smem_u32(const void* p) {
    return (uint32_t)__cvta_generic_to_shared(p);
}

__device__ __forceinline__ void ldsm_x4(uint32_t addr, uint32_t& r0, uint32_t& r1,
                                        uint32_t& r2, uint32_t& r3) {
    asm volatile("ldmatrix.sync.aligned.m8n8.x4.shared.b16 {%0,%1,%2,%3}, [%4];"
                 : "=r"(r0), "=r"(r1), "=r"(r2), "=r"(r3) : "r"(addr));
}

__device__ __forceinline__ void ldsm_x4t(uint32_t addr, uint32_t& r0, uint32_t& r1,
                                         uint32_t& r2, uint32_t& r3) {
    asm volatile("ldmatrix.sync.aligned.m8n8.x4.trans.shared.b16 {%0,%1,%2,%3}, [%4];"
                 : "=r"(r0), "=r"(r1), "=r"(r2), "=r"(r3) : "r"(addr));
}

__device__ __forceinline__ void mma16816(float* d, uint32_t a0, uint32_t a1,
                                         uint32_t a2, uint32_t a3,
                                         uint32_t b0, uint32_t b1) {
    asm volatile(
        "mma.sync.aligned.m16n8k16.row.col.f32.f16.f16.f32 "
        "{%0,%1,%2,%3}, {%4,%5,%6,%7}, {%8,%9}, {%0,%1,%2,%3};"
        : "+f"(d[0]), "+f"(d[1]), "+f"(d[2]), "+f"(d[3])
        : "r"(a0), "r"(a1), "r"(a2), "r"(a3), "r"(b0), "r"(b1));
}

__device__ __forceinline__ float4 ldcs4(const float4* p) {
    float4 v;
    asm volatile("ld.global.cs.v4.f32 {%0,%1,%2,%3}, [%4];"
                 : "=f"(v.x), "=f"(v.y), "=f"(v.z), "=f"(v.w) : "l"(p));
    return v;
}

__global__ void __launch_bounds__(512, 1) gnn_fused_kernel(
    const float* __restrict__ adj, const float* __restrict__ vec,
    const float* __restrict__ w1_rel, const float* __restrict__ w1_root,
    const float* __restrict__ b1,
    const float* __restrict__ w2_rel, const float* __restrict__ w2_root,
    const float* __restrict__ b2,
    const float* __restrict__ wf, const float* __restrict__ bf,
    float* __restrict__ out)
{
    extern __shared__ char smem[];
    __half* Vh   = (__half*)(smem + OFF_V);
    __half* Whi  = (__half*)(smem + OFF_WHI);
    __half* Wlo  = (__half*)(smem + OFF_WLO);
    float*  Pf   = (float*)(smem + OFF_P);
    float*  B1s  = (float*)(smem + OFF_B1);
    float*  A0s  = (float*)(smem + OFF_A0);
    float*  PART = (float*)(smem + OFF_PART);
    float*  SA   = (float*)(smem + OFF_SA);
    float*  SB   = (float*)(smem + OFF_SB);
    float*  W2s  = (float*)(smem + OFF_V);   // reused after MMA phase

    const int tid  = threadIdx.x;
    const int lane = tid & 31;
    const int wid  = tid >> 5;
    const int b    = blockIdx.x;

    // ---------------- Phase A: load vec (fp16) + split weights ----------------
    {
        const float4* v4 = (const float4*)(vec + (size_t)b * (NN * FF));
        for (int p = tid; p < (NN * FF) / 4; p += 512) {
            float4 x = v4[p];
            float comp[4] = {x.x, x.y, x.z, x.w};
            int idx = p * 4;
#pragma unroll
            for (int q = 0; q < 4; ++q) {
                int ii = idx + q;
                int r = ii / FF, c = ii - r * FF;
                Vh[r * 72 + c] = __float2half(comp[q]);
            }
        }
        if (tid < NN) Vh[tid * 72 + 63] = __float2half(0.0f);  // zero pad col 63

        for (int idx = tid; idx < FF * DD; idx += 512) {
            int k = idx >> 6, n = idx & 63;
            float wr = w1_rel[idx], wt = w1_root[idx];
            __half hr = __float2half(wr), ht = __float2half(wt);
            Whi[k * 136 + n]      = hr;
            Wlo[k * 136 + n]      = __float2half(wr - __half2float(hr));
            Whi[k * 136 + 64 + n] = ht;
            Wlo[k * 136 + 64 + n] = __float2half(wt - __half2float(ht));
        }
        if (tid < 128) {  // zero pad k=63 row
            Whi[63 * 136 + tid] = __float2half(0.0f);
            Wlo[63 * 136 + tid] = __float2half(0.0f);
        }
        if (tid < 64) B1s[tid] = b1[tid];
    }
    __syncthreads();

    // ------- Phase A2: P = Vh @ [Whi + Wlo] via mma.sync, 16 warps x 16 rows ---
    {
        const int row16 = lane & 15;
        const int half8 = (lane >> 4) << 3;  // 0 or 8
        const int mb = wid * 16;
#pragma unroll
        for (int nh = 0; nh < 2; ++nh) {     // n-half: cols nh*64 .. nh*64+63
            float acc[8][4];
#pragma unroll
            for (int q = 0; q < 8; ++q)
#pragma unroll
                for (int t = 0; t < 4; ++t) acc[q][t] = 0.0f;

#pragma unroll
            for (int kt = 0; kt < 4; ++kt) {
                uint32_t a0, a1, a2, a3;
                uint32_t aaddr = smem_u32(&Vh[(mb + row16) * 72 + kt * 16 + half8]);
                ldsm_x4(aaddr, a0, a1, a2, a3);
#pragma unroll
                for (int pass = 0; pass < 2; ++pass) {
                    const __half* Wb = pass ? Wlo : Whi;
#pragma unroll
                    for (int nt = 0; nt < 4; ++nt) {
                        uint32_t b0, b1r, b2r, b3r;
                        uint32_t baddr = smem_u32(
                            &Wb[(kt * 16 + row16) * 136 + nh * 64 + nt * 16 + half8]);
                        ldsm_x4t(baddr, b0, b1r, b2r, b3r);
                        mma16816(acc[2 * nt],     a0, a1, a2, a3, b0, b1r);
                        mma16816(acc[2 * nt + 1], a0, a1, a2, a3, b2r, b3r);
                    }
                }
            }
            const int r0 = mb + (lane >> 2);
            const int c0 = (lane & 3) * 2;
#pragma unroll
            for (int q = 0; q < 8; ++q) {
                *(float2*)&Pf[r0 * 136 + nh * 64 + q * 8 + c0] =
                    make_float2(acc[q][0], acc[q][1]);
                *(float2*)&Pf[(r0 + 8) * 136 + nh * 64 + q * 8 + c0] =
                    make_float2(acc[q][2], acc[q][3]);
            }
        }
    }
    __syncthreads();

    // ---------------- Phase B: stream adj, sparse-aggregate Hrel ----------------
    {
        // stage w2 weights + adj row 0 (Vh region is dead now)
        const float4* wr4 = (const float4*)w2_rel;
        const float4* wt4 = (const float4*)w2_root;
        for (int p = tid; p < 1024; p += 512) {
            ((float4*)W2s)[p]          = wr4[p];
            ((float4*)(W2s + 4096))[p] = wt4[p];
        }
        const float* arow0 = adj + (size_t)b * (NN * NN);
        if (tid < NN) A0s[tid] = arow0[tid];

        const float4* ab = (const float4*)(adj + (size_t)b * (NN * NN));
        const int base = wid * 16;

        // prefetch ring: depth 4
        float4 bufA[4], bufB[4];
#pragma unroll
        for (int r = 0; r < 4; ++r) {
            bufA[r] = ldcs4(&ab[(base + r) * 64 + lane]);
            bufB[r] = ldcs4(&ab[(base + r) * 64 + 32 + lane]);
        }

#pragma unroll 4
        for (int r = 0; r < 16; ++r) {
            const int i = base + r;
            float4 va = bufA[r & 3];
            float4 vb = bufB[r & 3];
            if (r < 12) {
                bufA[r & 3] = ldcs4(&ab[(i + 4) * 64 + lane]);
                bufB[r & 3] = ldcs4(&ab[(i + 4) * 64 + 32 + lane]);
            }

            float ax = 0.0f, ay = 0.0f;   // accumulator pair 0
            float bx2 = 0.0f, by2 = 0.0f; // accumulator pair 1 (ILP)
            float vals[8] = {va.x, va.y, va.z, va.w, vb.x, vb.y, vb.z, vb.w};
#pragma unroll
            for (int e = 0; e < 8; ++e) {
                float v = vals[e];
                unsigned m1 = __ballot_sync(0xffffffffu, v == 1.0f);
                unsigned m2 = __ballot_sync(0xffffffffu, v == 2.0f);
                const int eoff = (e < 4) ? e : (128 + e - 4);
                while (m1) {
                    int l0 = __ffs(m1) - 1;
                    m1 &= m1 - 1;
                    const float2 h0 =
                        *(const float2*)&Pf[(l0 * 4 + eoff) * 136 + 2 * lane];
                    ax += h0.x;
                    ay += h0.y;
                    if (m1) {
                        int l1 = __ffs(m1) - 1;
                        m1 &= m1 - 1;
                        const float2 h1 =
                            *(const float2*)&Pf[(l1 * 4 + eoff) * 136 + 2 * lane];
                        bx2 += h1.x;
                        by2 += h1.y;
                    }
                }
                while (m2) {  // rare: diagonal self-loop + random edge (value 2)
                    int l0 = __ffs(m2) - 1;
                    m2 &= m2 - 1;
                    const float2 h0 =
                        *(const float2*)&Pf[(l0 * 4 + eoff) * 136 + 2 * lane];
                    ax += 2.0f * h0.x;
                    ay += 2.0f * h0.y;
                }
            }
            float accx = ax + bx2, accy = ay + by2;

            // x[i] = relu(agg + Hroot + b1), stored in P cols 64..127
            float hr0 = Pf[i * 136 + 64 + 2 * lane]     + B1s[2 * lane];
            float hr1 = Pf[i * 136 + 64 + 2 * lane + 1] + B1s[2 * lane + 1];
            Pf[i * 136 + 64 + 2 * lane]     = fmaxf(accx + hr0, 0.0f);
            Pf[i * 136 + 64 + 2 * lane + 1] = fmaxf(accy + hr1, 0.0f);
        }
    }
    __syncthreads();

    // ---------------- Phase D: layer-2 readout at node 0 (exact fp32) ----------
    // SA = adj[0,:] @ x  (dense, 4-way split reduction)
    if (tid < 256) {
        const int g = tid >> 6, c = tid & 63;
        float s = 0.0f;
#pragma unroll 8
        for (int q = 0; q < 64; ++q) {
            const int j = g * 64 + q;
            s = fmaf(A0s[j], Pf[j * 136 + 64 + c], s);
        }
        PART[tid] = s;
    }
    __syncthreads();
    if (tid < 64)
        SA[tid] = PART[tid] + PART[64 + tid] + PART[128 + tid] + PART[192 + tid];
    __syncthreads();
    if (tid < 64) {
        float acc = b2[tid];
#pragma unroll 8
        for (int d = 0; d < 64; ++d)
            acc += SA[d] * W2s[d * 64 + tid] + Pf[64 + d] * W2s[4096 + d * 64 + tid];
        float y = fmaxf(acc, 0.0f);
        SB[tid] = y + Pf[64 + tid];  // x0 + y0
    }
    __syncthreads();
    if (tid < 2) {
        float s = bf[tid];
#pragma unroll 16
        for (int d = 0; d < 64; ++d) s = fmaf(SB[d], wf[d * 2 + tid], s);
        out[(size_t)b * 2 + tid] = s;
    }
}

extern "C" void kernel_launch(void* const* d_in, const int* in_sizes, int n_in,
                              void* d_out, int out_size) {
    const float* adj     = (const float*)d_in[0];
    const float* vec     = (const float*)d_in[1];
    const float* w1_rel  = (const float*)d_in[2];
    const float* w1_root = (const float*)d_in[3];
    const float* b1      = (const float*)d_in[4];
    const float* w2_rel  = (const float*)d_in[5];
    const float* w2_root = (const float*)d_in[6];
    const float* b2      = (const float*)d_in[7];
    const float* wf      = (const float*)d_in[8];
    const float* bf      = (const float*)d_in[9];
    float* out = (float*)d_out;

    cudaFuncSetAttribute(gnn_fused_kernel,
                         cudaFuncAttributeMaxDynamicSharedMemorySize, SMEM_BYTES);
    gnn_fused_kernel<<<NB, 512, SMEM_BYTES>>>(
        adj, vec, w1_rel, w1_root, b1, w2_rel, w2_root, b2, wf, bf, out);
}

// round 5
// speedup vs baseline: 2.1690x; 1.2035x over previous
#include <cuda_runtime.h>
#include <cuda_fp16.h>
#include <cstdint>

// Problem constants
#define NB 1024
#define NN 256
#define FF 63
#define DD 64

// smem byte offsets
#define OFF_STAGE 0        // half [256*72]: Vh in Phase A, per-warp A-staging in Phase B
#define OFF_WHI   36864    // half Whi[64][136] (Phase A); W2s fp32[8192] reuse (Phase B/D)
#define OFF_WLO   54272    // half Wlo[64][136]
#define OFF_HHI   71680    // half Hrel_hi[256][72]
#define OFF_HLO   108544   // half Hrel_lo[256][72]
#define OFF_XR    145408   // float [256][64]: Hroot (Phase A) -> x (Phase B)
#define OFF_B1    210944   // float[64]
#define OFF_A0    211200   // float[256] adj row 0
#define OFF_PART  212224   // float[256]
#define OFF_SA    213248   // float[64]
#define OFF_SB    213504   // float[64]
#define SMEM_BYTES 213760

__device__ __forceinline__ uint32_t smem_u32(const void* p) {
    return (uint32_t)__cvta_generic_to_shared(p);
}

__device__ __forceinline__ void ldsm_x4(uint32_t addr, uint32_t& r0, uint32_t& r1,
                                        uint32_t& r2, uint32_t& r3) {
    asm volatile("ldmatrix.sync.aligned.m8n8.x4.shared.b16 {%0,%1,%2,%3}, [%4];"
                 : "=r"(r0), "=r"(r1), "=r"(r2), "=r"(r3) : "r"(addr));
}

__device__ __forceinline__ void ldsm_x4t(uint32_t addr, uint32_t& r0, uint32_t& r1,
                                         uint32_t& r2, uint32_t& r3) {
    asm volatile("ldmatrix.sync.aligned.m8n8.x4.trans.shared.b16 {%0,%1,%2,%3}, [%4];"
                 : "=r"(r0), "=r"(r1), "=r"(r2), "=r"(r3) : "r"(addr));
}

__device__ __forceinline__ void mma16816(float* d, uint32_t a0, uint32_t a1,
                                         uint32_t a2, uint32_t a3,
                                         uint32_t b0, uint32_t b1) {
    asm volatile(
        "mma.sync.aligned.m16n8k16.row.col.f32.f16.f16.f32 "
        "{%0,%1,%2,%3}, {%4,%5,%6,%7}, {%8,%9}, {%0,%1,%2,%3};"
        : "+f"(d[0]), "+f"(d[1]), "+f"(d[2]), "+f"(d[3])
        : "r"(a0), "r"(a1), "r"(a2), "r"(a3), "r"(b0), "r"(b1));
}

__device__ __forceinline__ float4 ldcs4(const float4* p) {
    float4 v;
    asm volatile("ld.global.cs.v4.f32 {%0,%1,%2,%3}, [%4];"
                 : "=f"(v.x), "=f"(v.y), "=f"(v.z), "=f"(v.w) : "l"(p));
    return v;
}

__global__ void __launch_bounds__(512, 1) gnn_fused_kernel(
    const float* __restrict__ adj, const float* __restrict__ vec,
    const float* __restrict__ w1_rel, const float* __restrict__ w1_root,
    const float* __restrict__ b1,
    const float* __restrict__ w2_rel, const float* __restrict__ w2_root,
    const float* __restrict__ b2,
    const float* __restrict__ wf, const float* __restrict__ bf,
    float* __restrict__ out)
{
    extern __shared__ char smem[];
    __half* Vh   = (__half*)(smem + OFF_STAGE);
    __half* Whi  = (__half*)(smem + OFF_WHI);
    __half* Wlo  = (__half*)(smem + OFF_WLO);
    __half* Hhi  = (__half*)(smem + OFF_HHI);
    __half* Hlo  = (__half*)(smem + OFF_HLO);
    float*  XR   = (float*)(smem + OFF_XR);
    float*  B1s  = (float*)(smem + OFF_B1);
    float*  A0s  = (float*)(smem + OFF_A0);
    float*  PART = (float*)(smem + OFF_PART);
    float*  SA   = (float*)(smem + OFF_SA);
    float*  SB   = (float*)(smem + OFF_SB);
    float*  W2s  = (float*)(smem + OFF_WHI);  // reused after Phase A

    const int tid  = threadIdx.x;
    const int lane = tid & 31;
    const int wid  = tid >> 5;
    const int b    = blockIdx.x;

    // ---------------- Phase A: load vec (fp16) + split weights ----------------
    {
        const float4* v4 = (const float4*)(vec + (size_t)b * (NN * FF));
        for (int p = tid; p < (NN * FF) / 4; p += 512) {
            float4 x = v4[p];
            float comp[4] = {x.x, x.y, x.z, x.w};
            int idx = p * 4;
#pragma unroll
            for (int q = 0; q < 4; ++q) {
                int ii = idx + q;
                int r = ii / FF, c = ii - r * FF;
                Vh[r * 72 + c] = __float2half(comp[q]);
            }
        }
        if (tid < NN) Vh[tid * 72 + 63] = __float2half(0.0f);  // zero pad col 63

        for (int idx = tid; idx < FF * DD; idx += 512) {
            int k = idx >> 6, n = idx & 63;
            float wr = w1_rel[idx], wt = w1_root[idx];
            __half hr = __float2half(wr), ht = __float2half(wt);
            Whi[k * 136 + n]      = hr;
            Wlo[k * 136 + n]      = __float2half(wr - __half2float(hr));
            Whi[k * 136 + 64 + n] = ht;
            Wlo[k * 136 + 64 + n] = __float2half(wt - __half2float(ht));
        }
        if (tid < 128) {  // zero pad k=63 row
            Whi[63 * 136 + tid] = __float2half(0.0f);
            Wlo[63 * 136 + tid] = __float2half(0.0f);
        }
        if (tid < 64) B1s[tid] = b1[tid];
    }
    __syncthreads();

    const int row16 = lane & 15;
    const int half8 = (lane >> 4) << 3;  // 0 or 8

    // ------- Phase A2: P = Vh @ [Whi + Wlo] via mma.sync, 16 warps x 16 rows ---
    // nh=0 -> Hrel (stored fp16 hi/lo); nh=1 -> Hroot (stored fp32 in XR)
    {
        const int mb = wid * 16;
#pragma unroll
        for (int nh = 0; nh < 2; ++nh) {
            float acc[8][4];
#pragma unroll
            for (int q = 0; q < 8; ++q)
#pragma unroll
                for (int t = 0; t < 4; ++t) acc[q][t] = 0.0f;

#pragma unroll
            for (int kt = 0; kt < 4; ++kt) {
                uint32_t a0, a1, a2, a3;
                ldsm_x4(smem_u32(&Vh[(mb + row16) * 72 + kt * 16 + half8]),
                        a0, a1, a2, a3);
#pragma unroll
                for (int pass = 0; pass < 2; ++pass) {
                    const __half* Wb = pass ? Wlo : Whi;
#pragma unroll
                    for (int nt = 0; nt < 4; ++nt) {
                        uint32_t b0, b1r, b2r, b3r;
                        ldsm_x4t(smem_u32(
                            &Wb[(kt * 16 + row16) * 136 + nh * 64 + nt * 16 + half8]),
                            b0, b1r, b2r, b3r);
                        mma16816(acc[2 * nt],     a0, a1, a2, a3, b0, b1r);
                        mma16816(acc[2 * nt + 1], a0, a1, a2, a3, b2r, b3r);
                    }
                }
            }
            const int r0 = mb + (lane >> 2);
            const int c0 = (lane & 3) * 2;
            if (nh == 0) {
#pragma unroll
                for (int q = 0; q < 8; ++q) {
                    const int c = q * 8 + c0;
#pragma unroll
                    for (int hh = 0; hh < 2; ++hh) {
                        const int rr = r0 + 8 * hh;
                        float vx = acc[q][2 * hh], vy = acc[q][2 * hh + 1];
                        __half hx = __float2half_rn(vx), hy = __float2half_rn(vy);
                        *(half2*)&Hhi[rr * 72 + c] = __halves2half2(hx, hy);
                        *(half2*)&Hlo[rr * 72 + c] = __halves2half2(
                            __float2half_rn(vx - __half2float(hx)),
                            __float2half_rn(vy - __half2float(hy)));
                    }
                }
            } else {
#pragma unroll
                for (int q = 0; q < 8; ++q) {
                    const int c = q * 8 + c0;
                    *(float2*)&XR[r0 * 64 + c] = make_float2(acc[q][0], acc[q][1]);
                    *(float2*)&XR[(r0 + 8) * 64 + c] = make_float2(acc[q][2], acc[q][3]);
                }
            }
        }
    }
    __syncthreads();

    // ------- Phase B: agg = adj @ Hrel via dense fp16 MMA, K-tiled streaming ---
    {
        // stage w2 weights (Whi/Wlo region dead) + adj row 0
        const float4* wr4 = (const float4*)w2_rel;
        const float4* wt4 = (const float4*)w2_root;
        for (int p = tid; p < 1024; p += 512) {
            ((float4*)W2s)[p]          = wr4[p];
            ((float4*)(W2s + 4096))[p] = wt4[p];
        }
        if (tid < NN) A0s[tid] = adj[(size_t)b * (NN * NN) + tid];

        const float4* ab = (const float4*)(adj + (size_t)b * (NN * NN));
        __half* Ast = (__half*)(smem + OFF_STAGE) + wid * (16 * 72);
        const int mrow = wid * 16;
        const int lrow = lane >> 4;   // 0/1
        const int lcol = lane & 15;   // float4 index within 16

        float acc[8][4];
#pragma unroll
        for (int q = 0; q < 8; ++q)
#pragma unroll
            for (int t = 0; t < 4; ++t) acc[q][t] = 0.0f;

        // prefetch kt=0 (read-once stream: evict-first)
        float4 pre[8];
#pragma unroll
        for (int p = 0; p < 8; ++p)
            pre[p] = ldcs4(&ab[(size_t)(mrow + lrow + p * 2) * 64 + lcol]);

#pragma unroll
        for (int kt = 0; kt < 4; ++kt) {
            // convert fp32 -> fp16 and store to warp-private staging
#pragma unroll
            for (int p = 0; p < 8; ++p) {
                union { half2 h[2]; uint2 u; } pk;
                pk.h[0] = __floats2half2_rn(pre[p].x, pre[p].y);
                pk.h[1] = __floats2half2_rn(pre[p].z, pre[p].w);
                *(uint2*)&Ast[(lrow + p * 2) * 72 + lcol * 4] = pk.u;
            }
            __syncwarp();
            if (kt < 3) {
#pragma unroll
                for (int p = 0; p < 8; ++p)
                    pre[p] = ldcs4(&ab[(size_t)(mrow + lrow + p * 2) * 64 +
                                       (kt + 1) * 16 + lcol]);
            }
#pragma unroll
            for (int ks = 0; ks < 4; ++ks) {
                uint32_t a0, a1, a2, a3;
                ldsm_x4(smem_u32(&Ast[row16 * 72 + ks * 16 + half8]), a0, a1, a2, a3);
                const int krow = kt * 64 + ks * 16 + row16;
#pragma unroll
                for (int pass = 0; pass < 2; ++pass) {
                    const __half* Hb = pass ? Hlo : Hhi;
#pragma unroll
                    for (int nt = 0; nt < 4; ++nt) {
                        uint32_t b0, b1r, b2r, b3r;
                        ldsm_x4t(smem_u32(&Hb[krow * 72 + nt * 16 + half8]),
                                 b0, b1r, b2r, b3r);
                        mma16816(acc[2 * nt],     a0, a1, a2, a3, b0, b1r);
                        mma16816(acc[2 * nt + 1], a0, a1, a2, a3, b2r, b3r);
                    }
                }
            }
            __syncwarp();
        }

        // epilogue: x = relu(agg + Hroot + b1), overwrite XR
        const int r0 = mrow + (lane >> 2);
        const int c0 = (lane & 3) * 2;
#pragma unroll
        for (int q = 0; q < 8; ++q) {
            const int c = q * 8 + c0;
            float2 bb  = *(float2*)&B1s[c];
            float2 h0  = *(float2*)&XR[r0 * 64 + c];
            float2 h1  = *(float2*)&XR[(r0 + 8) * 64 + c];
            *(float2*)&XR[r0 * 64 + c] = make_float2(
                fmaxf(acc[q][0] + h0.x + bb.x, 0.0f),
                fmaxf(acc[q][1] + h0.y + bb.y, 0.0f));
            *(float2*)&XR[(r0 + 8) * 64 + c] = make_float2(
                fmaxf(acc[q][2] + h1.x + bb.x, 0.0f),
                fmaxf(acc[q][3] + h1.y + bb.y, 0.0f));
        }
    }
    __syncthreads();

    // ---------------- Phase D: layer-2 readout at node 0 (exact fp32) ----------
    if (tid < 256) {
        const int g = tid >> 6, c = tid & 63;
        float s = 0.0f;
#pragma unroll 8
        for (int q = 0; q < 64; ++q) {
            const int j = g * 64 + q;
            s = fmaf(A0s[j], XR[j * 64 + c], s);
        }
        PART[tid] = s;
    }
    __syncthreads();
    if (tid < 64)
        SA[tid] = PART[tid] + PART[64 + tid] + PART[128 + tid] + PART[192 + tid];
    __syncthreads();
    if (tid < 64) {
        float acc = b2[tid];
#pragma unroll 8
        for (int d = 0; d < 64; ++d)
            acc += SA[d] * W2s[d * 64 + tid] + XR[d] * W2s[4096 + d * 64 + tid];
        float y = fmaxf(acc, 0.0f);
        SB[tid] = y + XR[tid];  // x0 + y0
    }
    __syncthreads();
    if (tid < 2) {
        float s = bf[tid];
#pragma unroll 16
        for (int d = 0; d < 64; ++d) s = fmaf(SB[d], wf[d * 2 + tid], s);
        out[(size_t)b * 2 + tid] = s;
    }
}

extern "C" void kernel_launch(void* const* d_in, const int* in_sizes, int n_in,
                              void* d_out, int out_size) {
    const float* adj     = (const float*)d_in[0];
    const float* vec     = (const float*)d_in[1];
    const float* w1_rel  = (const float*)d_in[2];
    const float* w1_root = (const float*)d_in[3];
    const float* b1      = (const float*)d_in[4];
    const float* w2_rel  = (const float*)d_in[5];
    const float* w2_root = (const float*)d_in[6];
    const float* b2      = (const float*)d_in[7];
    const float* wf      = (const float*)d_in[8];
    const float* bf      = (const float*)d_in[9];
    float* out = (float*)d_out;

    cudaFuncSetAttribute(gnn_fused_kernel,
                         cudaFuncAttributeMaxDynamicSharedMemorySize, SMEM_BYTES);
    gnn_fused_kernel<<<NB, 512, SMEM_BYTES>>>(
        adj, vec, w1_rel, w1_root, b1, w2_rel, w2_root, b2, wf, bf, out);
}

// round 6
// speedup vs baseline: 2.6488x; 1.2212x over previous
#include <cuda_runtime.h>
#include <cuda_fp16.h>
#include <cstdint>

// Problem constants
#define NB 1024
#define NN 256
#define FF 63
#define DD 64

// smem byte offsets
#define OFF_VH   0        // half Vh[256][72]                      36864 B
#define OFF_WHI  36864    // half Whi[64][136] (rel|root)          17408 B
#define OFF_WLO  54272    // half Wlo[64][136]                     17408 B
#define OFF_STG  71680    // half stage[16 warps][16][72]          36864 B
#define OFF_XR   108544   // float x[256][64]                      65536 B
#define OFF_B1   174080   // float[64]
#define OFF_A0   174336   // float[256] adj row 0
#define OFF_PART 175360   // float[256]
#define OFF_SA   176384   // float[64]
#define OFF_SB   176640   // float[64]
#define SMEM_BYTES 176896

__device__ __forceinline__ uint32_t smem_u32(const void* p) {
    return (uint32_t)__cvta_generic_to_shared(p);
}

__device__ __forceinline__ void ldsm_x4(uint32_t addr, uint32_t& r0, uint32_t& r1,
                                        uint32_t& r2, uint32_t& r3) {
    asm volatile("ldmatrix.sync.aligned.m8n8.x4.shared.b16 {%0,%1,%2,%3}, [%4];"
                 : "=r"(r0), "=r"(r1), "=r"(r2), "=r"(r3) : "r"(addr));
}

__device__ __forceinline__ void ldsm_x4t(uint32_t addr, uint32_t& r0, uint32_t& r1,
                                         uint32_t& r2, uint32_t& r3) {
    asm volatile("ldmatrix.sync.aligned.m8n8.x4.trans.shared.b16 {%0,%1,%2,%3}, [%4];"
                 : "=r"(r0), "=r"(r1), "=r"(r2), "=r"(r3) : "r"(addr));
}

__device__ __forceinline__ void mma16816(float* d, uint32_t a0, uint32_t a1,
                                         uint32_t a2, uint32_t a3,
                                         uint32_t b0, uint32_t b1) {
    asm volatile(
        "mma.sync.aligned.m16n8k16.row.col.f32.f16.f16.f32 "
        "{%0,%1,%2,%3}, {%4,%5,%6,%7}, {%8,%9}, {%0,%1,%2,%3};"
        : "+f"(d[0]), "+f"(d[1]), "+f"(d[2]), "+f"(d[3])
        : "r"(a0), "r"(a1), "r"(a2), "r"(a3), "r"(b0), "r"(b1));
}

__device__ __forceinline__ float4 ldcs4(const float4* p) {
    float4 v;
    asm volatile("ld.global.cs.v4.f32 {%0,%1,%2,%3}, [%4];"
                 : "=f"(v.x), "=f"(v.y), "=f"(v.z), "=f"(v.w) : "l"(p));
    return v;
}

__global__ void __launch_bounds__(512, 1) gnn_fused_kernel(
    const float* __restrict__ adj, const float* __restrict__ vec,
    const float* __restrict__ w1_rel, const float* __restrict__ w1_root,
    const float* __restrict__ b1,
    const float* __restrict__ w2_rel, const float* __restrict__ w2_root,
    const float* __restrict__ b2,
    const float* __restrict__ wf, const float* __restrict__ bf,
    float* __restrict__ out)
{
    extern __shared__ char smem[];
    __half* Vh   = (__half*)(smem + OFF_VH);
    __half* Whi  = (__half*)(smem + OFF_WHI);
    __half* Wlo  = (__half*)(smem + OFF_WLO);
    float*  XR   = (float*)(smem + OFF_XR);
    float*  B1s  = (float*)(smem + OFF_B1);
    float*  A0s  = (float*)(smem + OFF_A0);
    float*  PART = (float*)(smem + OFF_PART);
    float*  SA   = (float*)(smem + OFF_SA);
    float*  SB   = (float*)(smem + OFF_SB);

    const int tid  = threadIdx.x;
    const int lane = tid & 31;
    const int wid  = tid >> 5;
    const int b    = blockIdx.x;

    // ---------------- Phase A: load Vh (fp16) + split weights + misc ----------
    {
        const float4* v4 = (const float4*)(vec + (size_t)b * (NN * FF));
        for (int p = tid; p < (NN * FF) / 4; p += 512) {
            float4 x = v4[p];
            float comp[4] = {x.x, x.y, x.z, x.w};
            int idx = p * 4;
#pragma unroll
            for (int q = 0; q < 4; ++q) {
                int ii = idx + q;
                int r = ii / FF, c = ii - r * FF;
                Vh[r * 72 + c] = __float2half(comp[q]);
            }
        }
        if (tid < NN) Vh[tid * 72 + 63] = __float2half(0.0f);  // zero pad col 63

        for (int idx = tid; idx < FF * DD; idx += 512) {
            int k = idx >> 6, n = idx & 63;
            float wr = w1_rel[idx], wt = w1_root[idx];
            __half hr = __float2half(wr), ht = __float2half(wt);
            Whi[k * 136 + n]      = hr;
            Wlo[k * 136 + n]      = __float2half(wr - __half2float(hr));
            Whi[k * 136 + 64 + n] = ht;
            Wlo[k * 136 + 64 + n] = __float2half(wt - __half2float(ht));
        }
        if (tid < 128) {  // zero pad k=63 row
            Whi[63 * 136 + tid] = __float2half(0.0f);
            Wlo[63 * 136 + tid] = __float2half(0.0f);
        }
        if (tid < 64) B1s[tid] = b1[tid];
        if (tid < NN) A0s[tid] = adj[(size_t)b * (NN * NN) + tid];
    }
    __syncthreads();

    const int row16 = lane & 15;
    const int half8 = (lane >> 4) << 3;  // 0 or 8
    const int mb = wid * 16;
    __half* Ast = (__half*)(smem + OFF_STG) + wid * (16 * 72);

    // ------- Phase B: T = adj @ Vh  (exact, single-pass B), K-tiled stream -----
    float accT[8][4];
#pragma unroll
    for (int q = 0; q < 8; ++q)
#pragma unroll
        for (int t = 0; t < 4; ++t) accT[q][t] = 0.0f;

    {
        const float4* ab = (const float4*)(adj + (size_t)b * (NN * NN));
        const int lrow = lane >> 4;   // 0/1
        const int lcol = lane & 15;   // float4 index within 16 (=64 floats)

        float4 pre[8];
#pragma unroll
        for (int p = 0; p < 8; ++p)
            pre[p] = ldcs4(&ab[(size_t)(mb + lrow + p * 2) * 64 + lcol]);

#pragma unroll
        for (int kt = 0; kt < 4; ++kt) {
            // convert fp32 -> fp16 into warp-private staging
#pragma unroll
            for (int p = 0; p < 8; ++p) {
                union { half2 h[2]; uint2 u; } pk;
                pk.h[0] = __floats2half2_rn(pre[p].x, pre[p].y);
                pk.h[1] = __floats2half2_rn(pre[p].z, pre[p].w);
                *(uint2*)&Ast[(lrow + p * 2) * 72 + lcol * 4] = pk.u;
            }
            __syncwarp();
            if (kt < 3) {
#pragma unroll
                for (int p = 0; p < 8; ++p)
                    pre[p] = ldcs4(&ab[(size_t)(mb + lrow + p * 2) * 64 +
                                       (kt + 1) * 16 + lcol]);
            }
#pragma unroll
            for (int ks = 0; ks < 4; ++ks) {
                uint32_t a0, a1, a2, a3;
                ldsm_x4(smem_u32(&Ast[row16 * 72 + ks * 16 + half8]), a0, a1, a2, a3);
                const int krow = kt * 64 + ks * 16 + row16;
#pragma unroll
                for (int nt = 0; nt < 4; ++nt) {
                    uint32_t b0, b1r, b2r, b3r;
                    ldsm_x4t(smem_u32(&Vh[krow * 72 + nt * 16 + half8]),
                             b0, b1r, b2r, b3r);
                    mma16816(accT[2 * nt],     a0, a1, a2, a3, b0, b1r);
                    mma16816(accT[2 * nt + 1], a0, a1, a2, a3, b2r, b3r);
                }
            }
            __syncwarp();
        }
    }

    // ------- Phase C: accX = Vh@w1_root (hi+lo) + T@w1_rel (3-pass split) ------
    float accX[8][4];
#pragma unroll
    for (int q = 0; q < 8; ++q)
#pragma unroll
        for (int t = 0; t < 4; ++t) accX[q][t] = 0.0f;

    {
        // Hroot: A = Vh own rows (exact fp16), B = W root cols (hi+lo)
        uint32_t af[4][4];
#pragma unroll
        for (int ks = 0; ks < 4; ++ks)
            ldsm_x4(smem_u32(&Vh[(mb + row16) * 72 + ks * 16 + half8]),
                    af[ks][0], af[ks][1], af[ks][2], af[ks][3]);
#pragma unroll
        for (int pass = 0; pass < 2; ++pass) {
            const __half* Wb = pass ? Wlo : Whi;
#pragma unroll
            for (int ks = 0; ks < 4; ++ks)
#pragma unroll
                for (int nt = 0; nt < 4; ++nt) {
                    uint32_t b0, b1r, b2r, b3r;
                    ldsm_x4t(smem_u32(
                        &Wb[(ks * 16 + row16) * 136 + 64 + nt * 16 + half8]),
                        b0, b1r, b2r, b3r);
                    mma16816(accX[2 * nt],     af[ks][0], af[ks][1], af[ks][2],
                             af[ks][3], b0, b1r);
                    mma16816(accX[2 * nt + 1], af[ks][0], af[ks][1], af[ks][2],
                             af[ks][3], b2r, b3r);
                }
        }

        const int rloc = lane >> 2;          // 0..7
        const int c0   = (lane & 3) * 2;

        // ---- pass set 1: Thi @ (Whi + Wlo) ----
#pragma unroll
        for (int q = 0; q < 8; ++q) {
            const int c = q * 8 + c0;
#pragma unroll
            for (int hh = 0; hh < 2; ++hh) {
                float vx = accT[q][2 * hh], vy = accT[q][2 * hh + 1];
                *(half2*)&Ast[(rloc + 8 * hh) * 72 + c] =
                    __halves2half2(__float2half_rn(vx), __float2half_rn(vy));
            }
        }
        __syncwarp();
#pragma unroll
        for (int ks = 0; ks < 4; ++ks)
            ldsm_x4(smem_u32(&Ast[row16 * 72 + ks * 16 + half8]),
                    af[ks][0], af[ks][1], af[ks][2], af[ks][3]);
        __syncwarp();
#pragma unroll
        for (int pass = 0; pass < 2; ++pass) {
            const __half* Wb = pass ? Wlo : Whi;
#pragma unroll
            for (int ks = 0; ks < 4; ++ks)
#pragma unroll
                for (int nt = 0; nt < 4; ++nt) {
                    uint32_t b0, b1r, b2r, b3r;
                    ldsm_x4t(smem_u32(
                        &Wb[(ks * 16 + row16) * 136 + nt * 16 + half8]),
                        b0, b1r, b2r, b3r);
                    mma16816(accX[2 * nt],     af[ks][0], af[ks][1], af[ks][2],
                             af[ks][3], b0, b1r);
                    mma16816(accX[2 * nt + 1], af[ks][0], af[ks][1], af[ks][2],
                             af[ks][3], b2r, b3r);
                }
        }

        // ---- pass set 2: Tlo @ Whi ----
#pragma unroll
        for (int q = 0; q < 8; ++q) {
            const int c = q * 8 + c0;
#pragma unroll
            for (int hh = 0; hh < 2; ++hh) {
                float vx = accT[q][2 * hh], vy = accT[q][2 * hh + 1];
                __half hx = __float2half_rn(vx), hy = __float2half_rn(vy);
                *(half2*)&Ast[(rloc + 8 * hh) * 72 + c] = __halves2half2(
                    __float2half_rn(vx - __half2float(hx)),
                    __float2half_rn(vy - __half2float(hy)));
            }
        }
        __syncwarp();
#pragma unroll
        for (int ks = 0; ks < 4; ++ks)
            ldsm_x4(smem_u32(&Ast[row16 * 72 + ks * 16 + half8]),
                    af[ks][0], af[ks][1], af[ks][2], af[ks][3]);
#pragma unroll
        for (int ks = 0; ks < 4; ++ks)
#pragma unroll
            for (int nt = 0; nt < 4; ++nt) {
                uint32_t b0, b1r, b2r, b3r;
                ldsm_x4t(smem_u32(&Whi[(ks * 16 + row16) * 136 + nt * 16 + half8]),
                         b0, b1r, b2r, b3r);
                mma16816(accX[2 * nt],     af[ks][0], af[ks][1], af[ks][2],
                         af[ks][3], b0, b1r);
                mma16816(accX[2 * nt + 1], af[ks][0], af[ks][1], af[ks][2],
                         af[ks][3], b2r, b3r);
            }

        // epilogue: x = relu(accX + b1) -> XR
        const int r0 = mb + (lane >> 2);
#pragma unroll
        for (int q = 0; q < 8; ++q) {
            const int c = q * 8 + c0;
            float2 bb = *(float2*)&B1s[c];
            *(float2*)&XR[r0 * 64 + c] = make_float2(
                fmaxf(accX[q][0] + bb.x, 0.0f), fmaxf(accX[q][1] + bb.y, 0.0f));
            *(float2*)&XR[(r0 + 8) * 64 + c] = make_float2(
                fmaxf(accX[q][2] + bb.x, 0.0f), fmaxf(accX[q][3] + bb.y, 0.0f));
        }
    }
    __syncthreads();

    // ---------------- Phase D: layer-2 readout at node 0 (exact fp32) ----------
    if (tid < 256) {
        const int g = tid >> 6, c = tid & 63;
        float s = 0.0f;
#pragma unroll 8
        for (int q = 0; q < 64; ++q) {
            const int j = g * 64 + q;
            s = fmaf(A0s[j], XR[j * 64 + c], s);
        }
        PART[tid] = s;
    }
    __syncthreads();
    if (tid < 64)
        SA[tid] = PART[tid] + PART[64 + tid] + PART[128 + tid] + PART[192 + tid];
    __syncthreads();
    if (tid < 64) {
        float acc = b2[tid];
#pragma unroll 8
        for (int d = 0; d < 64; ++d)
            acc += SA[d] * w2_rel[d * 64 + tid] + XR[d] * w2_root[d * 64 + tid];
        float y = fmaxf(acc, 0.0f);
        SB[tid] = y + XR[tid];  // x0 + y0
    }
    __syncthreads();
    if (tid < 2) {
        float s = bf[tid];
#pragma unroll 16
        for (int d = 0; d < 64; ++d) s = fmaf(SB[d], wf[d * 2 + tid], s);
        out[(size_t)b * 2 + tid] = s;
    }
}

extern "C" void kernel_launch(void* const* d_in, const int* in_sizes, int n_in,
                              void* d_out, int out_size) {
    const float* adj     = (const float*)d_in[0];
    const float* vec     = (const float*)d_in[1];
    const float* w1_rel  = (const float*)d_in[2];
    const float* w1_root = (const float*)d_in[3];
    const float* b1      = (const float*)d_in[4];
    const float* w2_rel  = (const float*)d_in[5];
    const float* w2_root = (const float*)d_in[6];
    const float* b2      = (const float*)d_in[7];
    const float* wf      = (const float*)d_in[8];
    const float* bf      = (const float*)d_in[9];
    float* out = (float*)d_out;

    cudaFuncSetAttribute(gnn_fused_kernel,
                         cudaFuncAttributeMaxDynamicSharedMemorySize, SMEM_BYTES);
    gnn_fused_kernel<<<NB, 512, SMEM_BYTES>>>(
        adj, vec, w1_rel, w1_root, b1, w2_rel, w2_root, b2, wf, bf, out);
}

// round 7
// speedup vs baseline: 3.2637x; 1.2322x over previous
#include <cuda_runtime.h>
#include <cuda_fp16.h>
#include <cstdint>

// Problem constants
#define NB 1024
#define NN 256
#define FF 63
#define DD 64

// smem byte offsets
#define OFF_VH   0        // half Vh[256][72]                 36864 B
#define OFF_WHI  36864    // half Whi[64][136] (rel|root)     17408 B
#define OFF_STG  54272    // half stage[16 warps][16][72]     36864 B
#define OFF_B1   91136    // float[64]
#define OFF_A0   91392    // float[256] adj row 0
#define OFF_PART 92416    // float[16][64] per-warp SA partials
#define OFF_X0   96512    // float[64] x row 0
#define OFF_SA   96768    // float[64]
#define OFF_SB   97024    // float[64]
#define SMEM_BYTES 97280

__device__ __forceinline__ uint32_t smem_u32(const void* p) {
    return (uint32_t)__cvta_generic_to_shared(p);
}

__device__ __forceinline__ void ldsm_x4(uint32_t addr, uint32_t& r0, uint32_t& r1,
                                        uint32_t& r2, uint32_t& r3) {
    asm volatile("ldmatrix.sync.aligned.m8n8.x4.shared.b16 {%0,%1,%2,%3}, [%4];"
                 : "=r"(r0), "=r"(r1), "=r"(r2), "=r"(r3) : "r"(addr));
}

__device__ __forceinline__ void ldsm_x4t(uint32_t addr, uint32_t& r0, uint32_t& r1,
                                         uint32_t& r2, uint32_t& r3) {
    asm volatile("ldmatrix.sync.aligned.m8n8.x4.trans.shared.b16 {%0,%1,%2,%3}, [%4];"
                 : "=r"(r0), "=r"(r1), "=r"(r2), "=r"(r3) : "r"(addr));
}

__device__ __forceinline__ void mma16816(float* d, uint32_t a0, uint32_t a1,
                                         uint32_t a2, uint32_t a3,
                                         uint32_t b0, uint32_t b1) {
    asm volatile(
        "mma.sync.aligned.m16n8k16.row.col.f32.f16.f16.f32 "
        "{%0,%1,%2,%3}, {%4,%5,%6,%7}, {%8,%9}, {%0,%1,%2,%3};"
        : "+f"(d[0]), "+f"(d[1]), "+f"(d[2]), "+f"(d[3])
        : "r"(a0), "r"(a1), "r"(a2), "r"(a3), "r"(b0), "r"(b1));
}

__device__ __forceinline__ float4 ldcs4(const float4* p) {
    float4 v;
    asm volatile("ld.global.cs.v4.f32 {%0,%1,%2,%3}, [%4];"
                 : "=f"(v.x), "=f"(v.y), "=f"(v.z), "=f"(v.w) : "l"(p));
    return v;
}

__global__ void __launch_bounds__(512, 1) gnn_fused_kernel(
    const float* __restrict__ adj, const float* __restrict__ vec,
    const float* __restrict__ w1_rel, const float* __restrict__ w1_root,
    const float* __restrict__ b1,
    const float* __restrict__ w2_rel, const float* __restrict__ w2_root,
    const float* __restrict__ b2,
    const float* __restrict__ wf, const float* __restrict__ bf,
    float* __restrict__ out)
{
    extern __shared__ char smem[];
    __half* Vh   = (__half*)(smem + OFF_VH);
    __half* Whi  = (__half*)(smem + OFF_WHI);
    float*  B1s  = (float*)(smem + OFF_B1);
    float*  A0s  = (float*)(smem + OFF_A0);
    float*  PART = (float*)(smem + OFF_PART);
    float*  X0s  = (float*)(smem + OFF_X0);
    float*  SAs  = (float*)(smem + OFF_SA);
    float*  SBs  = (float*)(smem + OFF_SB);

    const int tid  = threadIdx.x;
    const int lane = tid & 31;
    const int wid  = tid >> 5;
    const int b    = blockIdx.x;

    const int row16 = lane & 15;
    const int half8 = (lane >> 4) << 3;  // 0 or 8
    const int mb = wid * 16;
    __half* Ast = (__half*)(smem + OFF_STG) + wid * (16 * 72);

    // -------- Entry prefetch: kt=0 of the adj stream, in flight during Phase A
    const float4* ab = (const float4*)(adj + (size_t)b * (NN * NN));
    const int lrow = lane >> 4;   // 0/1
    const int lcol = lane & 15;   // float4 index within 16 (=64 floats)
    float4 pre[8];
#pragma unroll
    for (int p = 0; p < 8; ++p)
        pre[p] = ldcs4(&ab[(size_t)(mb + lrow + p * 2) * 64 + lcol]);

    // ---------------- Phase A: load Vh (fp16) + Whi weights + misc ------------
    {
        const float4* v4 = (const float4*)(vec + (size_t)b * (NN * FF));
        for (int p = tid; p < (NN * FF) / 4; p += 512) {
            float4 x = v4[p];
            float comp[4] = {x.x, x.y, x.z, x.w};
            int idx = p * 4;
#pragma unroll
            for (int q = 0; q < 4; ++q) {
                int ii = idx + q;
                int r = ii / FF, c = ii - r * FF;
                Vh[r * 72 + c] = __float2half(comp[q]);
            }
        }
        if (tid < NN) Vh[tid * 72 + 63] = __float2half(0.0f);  // zero pad col 63

        for (int idx = tid; idx < FF * DD; idx += 512) {
            int k = idx >> 6, n = idx & 63;
            Whi[k * 136 + n]      = __float2half(w1_rel[idx]);
            Whi[k * 136 + 64 + n] = __float2half(w1_root[idx]);
        }
        if (tid < 128) Whi[63 * 136 + tid] = __float2half(0.0f);  // pad k=63
        if (tid < 64) B1s[tid] = b1[tid];
        if (tid < NN) A0s[tid] = adj[(size_t)b * (NN * NN) + tid];
    }
    __syncthreads();

    // ------- Phase B: T = adj @ Vh  (exact, single-pass B), K-tiled stream -----
    float accT[8][4];
#pragma unroll
    for (int q = 0; q < 8; ++q)
#pragma unroll
        for (int t = 0; t < 4; ++t) accT[q][t] = 0.0f;

    {
#pragma unroll
        for (int kt = 0; kt < 4; ++kt) {
            // convert fp32 -> fp16 into warp-private staging
#pragma unroll
            for (int p = 0; p < 8; ++p) {
                union { half2 h[2]; uint2 u; } pk;
                pk.h[0] = __floats2half2_rn(pre[p].x, pre[p].y);
                pk.h[1] = __floats2half2_rn(pre[p].z, pre[p].w);
                *(uint2*)&Ast[(lrow + p * 2) * 72 + lcol * 4] = pk.u;
            }
            __syncwarp();
            if (kt < 3) {
#pragma unroll
                for (int p = 0; p < 8; ++p)
                    pre[p] = ldcs4(&ab[(size_t)(mb + lrow + p * 2) * 64 +
                                       (kt + 1) * 16 + lcol]);
            }
#pragma unroll
            for (int ks = 0; ks < 4; ++ks) {
                uint32_t a0, a1, a2, a3;
                ldsm_x4(smem_u32(&Ast[row16 * 72 + ks * 16 + half8]), a0, a1, a2, a3);
                const int krow = kt * 64 + ks * 16 + row16;
#pragma unroll
                for (int nt = 0; nt < 4; ++nt) {
                    uint32_t b0, b1r, b2r, b3r;
                    ldsm_x4t(smem_u32(&Vh[krow * 72 + nt * 16 + half8]),
                             b0, b1r, b2r, b3r);
                    mma16816(accT[2 * nt],     a0, a1, a2, a3, b0, b1r);
                    mma16816(accT[2 * nt + 1], a0, a1, a2, a3, b2r, b3r);
                }
            }
            __syncwarp();
        }
    }

    // ------- Phase C: accX = Vh@Whi_root + Thi@Whi_rel (2 pass-sets) -----------
    float accX[8][4];
#pragma unroll
    for (int q = 0; q < 8; ++q)
#pragma unroll
        for (int t = 0; t < 4; ++t) accX[q][t] = 0.0f;

    {
        uint32_t af[4][4];
        // root term: A = Vh own rows
#pragma unroll
        for (int ks = 0; ks < 4; ++ks)
            ldsm_x4(smem_u32(&Vh[(mb + row16) * 72 + ks * 16 + half8]),
                    af[ks][0], af[ks][1], af[ks][2], af[ks][3]);
#pragma unroll
        for (int ks = 0; ks < 4; ++ks)
#pragma unroll
            for (int nt = 0; nt < 4; ++nt) {
                uint32_t b0, b1r, b2r, b3r;
                ldsm_x4t(smem_u32(
                    &Whi[(ks * 16 + row16) * 136 + 64 + nt * 16 + half8]),
                    b0, b1r, b2r, b3r);
                mma16816(accX[2 * nt],     af[ks][0], af[ks][1], af[ks][2],
                         af[ks][3], b0, b1r);
                mma16816(accX[2 * nt + 1], af[ks][0], af[ks][1], af[ks][2],
                         af[ks][3], b2r, b3r);
            }

        // rel term: stage Thi, A = Thi
        const int rloc = lane >> 2;          // 0..7
        const int c0   = (lane & 3) * 2;
#pragma unroll
        for (int q = 0; q < 8; ++q) {
            const int c = q * 8 + c0;
#pragma unroll
            for (int hh = 0; hh < 2; ++hh) {
                float vx = accT[q][2 * hh], vy = accT[q][2 * hh + 1];
                *(half2*)&Ast[(rloc + 8 * hh) * 72 + c] =
                    __halves2half2(__float2half_rn(vx), __float2half_rn(vy));
            }
        }
        __syncwarp();
#pragma unroll
        for (int ks = 0; ks < 4; ++ks)
            ldsm_x4(smem_u32(&Ast[row16 * 72 + ks * 16 + half8]),
                    af[ks][0], af[ks][1], af[ks][2], af[ks][3]);
#pragma unroll
        for (int ks = 0; ks < 4; ++ks)
#pragma unroll
            for (int nt = 0; nt < 4; ++nt) {
                uint32_t b0, b1r, b2r, b3r;
                ldsm_x4t(smem_u32(&Whi[(ks * 16 + row16) * 136 + nt * 16 + half8]),
                         b0, b1r, b2r, b3r);
                mma16816(accX[2 * nt],     af[ks][0], af[ks][1], af[ks][2],
                         af[ks][3], b0, b1r);
                mma16816(accX[2 * nt + 1], af[ks][0], af[ks][1], af[ks][2],
                         af[ks][3], b2r, b3r);
            }

        // ---- epilogue: x = relu(accX+b1); fold node-0 readout in registers ----
        const int r0 = mb + rloc;
        const float a0lo = A0s[r0];
        const float a0hi = A0s[r0 + 8];
        float part[16];
#pragma unroll
        for (int q = 0; q < 8; ++q) {
            const int c = q * 8 + c0;
            float2 bb = *(float2*)&B1s[c];
            float x00 = fmaxf(accX[q][0] + bb.x, 0.0f);
            float x01 = fmaxf(accX[q][1] + bb.y, 0.0f);
            float x80 = fmaxf(accX[q][2] + bb.x, 0.0f);
            float x81 = fmaxf(accX[q][3] + bb.y, 0.0f);
            part[2 * q]     = a0lo * x00 + a0hi * x80;
            part[2 * q + 1] = a0lo * x01 + a0hi * x81;
            if (wid == 0 && rloc == 0) {   // x row 0 lives in lanes 0-3 of warp 0
                X0s[c]     = x00;
                X0s[c + 1] = x01;
            }
        }
        // reduce over the 8 row-groups (lanes differing in bits 2..4)
#pragma unroll
        for (int off = 4; off <= 16; off <<= 1)
#pragma unroll
            for (int t = 0; t < 16; ++t)
                part[t] += __shfl_xor_sync(0xffffffffu, part[t], off);
        if (lane < 4) {
#pragma unroll
            for (int q = 0; q < 8; ++q) {
                PART[wid * 64 + q * 8 + c0]     = part[2 * q];
                PART[wid * 64 + q * 8 + c0 + 1] = part[2 * q + 1];
            }
        }
    }
    __syncthreads();

    // ---------------- Final head: layer 2 at node 0 + linear head --------------
    if (tid < 64) {
        float s = 0.0f;
#pragma unroll
        for (int w = 0; w < 16; ++w) s += PART[w * 64 + tid];
        SAs[tid] = s;   // SA = adj[0,:] @ x
    }
    __syncthreads();
    if (tid < 64) {
        float acc = b2[tid];
#pragma unroll 8
        for (int d = 0; d < 64; ++d)
            acc += SAs[d] * w2_rel[d * 64 + tid] + X0s[d] * w2_root[d * 64 + tid];
        float y = fmaxf(acc, 0.0f);
        SBs[tid] = y + X0s[tid];  // x0 + y0
    }
    __syncthreads();
    if (tid < 2) {
        float s = bf[tid];
#pragma unroll 16
        for (int d = 0; d < 64; ++d) s = fmaf(SBs[d], wf[d * 2 + tid], s);
        out[(size_t)b * 2 + tid] = s;
    }
}

extern "C" void kernel_launch(void* const* d_in, const int* in_sizes, int n_in,
                              void* d_out, int out_size) {
    const float* adj     = (const float*)d_in[0];
    const float* vec     = (const float*)d_in[1];
    const float* w1_rel  = (const float*)d_in[2];
    const float* w1_root = (const float*)d_in[3];
    const float* b1      = (const float*)d_in[4];
    const float* w2_rel  = (const float*)d_in[5];
    const float* w2_root = (const float*)d_in[6];
    const float* b2      = (const float*)d_in[7];
    const float* wf      = (const float*)d_in[8];
    const float* bf      = (const float*)d_in[9];
    float* out = (float*)d_out;

    cudaFuncSetAttribute(gnn_fused_kernel,
                         cudaFuncAttributeMaxDynamicSharedMemorySize, SMEM_BYTES);
    gnn_fused_kernel<<<NB, 512, SMEM_BYTES>>>(
        adj, vec, w1_rel, w1_root, b1, w2_rel, w2_root, b2, wf, bf, out);
}

// round 8
// speedup vs baseline: 3.3575x; 1.0287x over previous
#include <cuda_runtime.h>
#include <cuda_fp16.h>
#include <cstdint>

// Problem constants
#define NB 1024
#define NN 256
#define FF 63
#define DD 64

// smem byte offsets (per CTA; 2 CTAs resident per SM)
#define OFF_VH   0        // half Vh[256][72]                 36864 B
#define OFF_WHI  36864    // half Whi[64][136] (rel|root)     17408 B
#define OFF_STG  54272    // half stage[8 warps][4608 B]      36864 B
#define OFF_B1   91136    // float[64]
#define OFF_A0   91392    // float[256] adj row 0
#define OFF_PART 92416    // float[8][64] per-warp SA partials
#define OFF_X0   94464    // float[64] x row 0
#define OFF_SA   94720    // float[64]
#define OFF_SB   94976    // float[64]
#define SMEM_BYTES 95232

#define STG_WARP_BYTES 4608   // >= max(32*40*2 (Phase B), 32*72*2 (Thi))

__device__ __forceinline__ uint32_t smem_u32(const void* p) {
    return (uint32_t)__cvta_generic_to_shared(p);
}

__device__ __forceinline__ void ldsm_x4(uint32_t addr, uint32_t& r0, uint32_t& r1,
                                        uint32_t& r2, uint32_t& r3) {
    asm volatile("ldmatrix.sync.aligned.m8n8.x4.shared.b16 {%0,%1,%2,%3}, [%4];"
                 : "=r"(r0), "=r"(r1), "=r"(r2), "=r"(r3) : "r"(addr));
}

__device__ __forceinline__ void ldsm_x4t(uint32_t addr, uint32_t& r0, uint32_t& r1,
                                         uint32_t& r2, uint32_t& r3) {
    asm volatile("ldmatrix.sync.aligned.m8n8.x4.trans.shared.b16 {%0,%1,%2,%3}, [%4];"
                 : "=r"(r0), "=r"(r1), "=r"(r2), "=r"(r3) : "r"(addr));
}

__device__ __forceinline__ void mma16816(float* d, uint32_t a0, uint32_t a1,
                                         uint32_t a2, uint32_t a3,
                                         uint32_t b0, uint32_t b1) {
    asm volatile(
        "mma.sync.aligned.m16n8k16.row.col.f32.f16.f16.f32 "
        "{%0,%1,%2,%3}, {%4,%5,%6,%7}, {%8,%9}, {%0,%1,%2,%3};"
        : "+f"(d[0]), "+f"(d[1]), "+f"(d[2]), "+f"(d[3])
        : "r"(a0), "r"(a1), "r"(a2), "r"(a3), "r"(b0), "r"(b1));
}

__device__ __forceinline__ float4 ldcs4(const float4* p) {
    float4 v;
    asm volatile("ld.global.cs.v4.f32 {%0,%1,%2,%3}, [%4];"
                 : "=f"(v.x), "=f"(v.y), "=f"(v.z), "=f"(v.w) : "l"(p));
    return v;
}

__global__ void __launch_bounds__(256, 2) gnn_fused_kernel(
    const float* __restrict__ adj, const float* __restrict__ vec,
    const float* __restrict__ w1_rel, const float* __restrict__ w1_root,
    const float* __restrict__ b1,
    const float* __restrict__ w2_rel, const float* __restrict__ w2_root,
    const float* __restrict__ b2,
    const float* __restrict__ wf, const float* __restrict__ bf,
    float* __restrict__ out)
{
    extern __shared__ char smem[];
    __half* Vh   = (__half*)(smem + OFF_VH);
    __half* Whi  = (__half*)(smem + OFF_WHI);
    float*  B1s  = (float*)(smem + OFF_B1);
    float*  A0s  = (float*)(smem + OFF_A0);
    float*  PART = (float*)(smem + OFF_PART);
    float*  X0s  = (float*)(smem + OFF_X0);
    float*  SAs  = (float*)(smem + OFF_SA);
    float*  SBs  = (float*)(smem + OFF_SB);

    const int tid  = threadIdx.x;
    const int lane = tid & 31;
    const int wid  = tid >> 5;
    const int b    = blockIdx.x;

    const int row16 = lane & 15;
    const int half8 = (lane >> 4) << 3;  // 0 or 8
    const int mb = wid * 32;             // 8 warps x 32 rows
    __half* stg = (__half*)(smem + OFF_STG + wid * STG_WARP_BYTES);

    // load-lane mapping for adj stream (rows of 64 float4)
    const int lrow = lane >> 3;   // 0..3
    const int lc4  = lane & 7;    // 0..7 (float4 col within 32-k step)

    // -------- Entry prefetch: step 0 of the adj stream (in flight during A) ----
    const float4* ab = (const float4*)(adj + (size_t)b * (NN * NN));
    float4 pre[8];
#pragma unroll
    for (int p = 0; p < 8; ++p)
        pre[p] = ldcs4(&ab[(size_t)(mb + p * 4 + lrow) * 64 + lc4]);

    // ---------------- Phase A: load Vh (fp16) + Whi weights + misc ------------
    {
        const float4* v4 = (const float4*)(vec + (size_t)b * (NN * FF));
        for (int p = tid; p < (NN * FF) / 4; p += 256) {
            float4 x = v4[p];
            float comp[4] = {x.x, x.y, x.z, x.w};
            int idx = p * 4;
#pragma unroll
            for (int q = 0; q < 4; ++q) {
                int ii = idx + q;
                int r = ii / FF, c = ii - r * FF;
                Vh[r * 72 + c] = __float2half(comp[q]);
            }
        }
        if (tid < NN) Vh[tid * 72 + 63] = __float2half(0.0f);  // zero pad col 63

        for (int idx = tid; idx < FF * DD; idx += 256) {
            int k = idx >> 6, n = idx & 63;
            Whi[k * 136 + n]      = __float2half(w1_rel[idx]);
            Whi[k * 136 + 64 + n] = __float2half(w1_root[idx]);
        }
        if (tid < 128) Whi[63 * 136 + tid] = __float2half(0.0f);  // pad k=63
        if (tid < 64) B1s[tid] = b1[tid];
        if (tid < NN) A0s[tid] = adj[(size_t)b * (NN * NN) + tid];
    }
    __syncthreads();

    // ------- Phase B: T = adj @ Vh (exact), 8 k-steps of 32, reg ring ----------
    float accT[2][8][4];   // [m-tile][col-octet][quad] : 32 rows x 64 cols
#pragma unroll
    for (int mt = 0; mt < 2; ++mt)
#pragma unroll
        for (int q = 0; q < 8; ++q)
#pragma unroll
            for (int t = 0; t < 4; ++t) accT[mt][q][t] = 0.0f;

#pragma unroll
    for (int s = 0; s < 8; ++s) {
        // stage 32 rows x 32 k as fp16, stride 40 halves
#pragma unroll
        for (int p = 0; p < 8; ++p) {
            union { half2 h[2]; uint2 u; } pk;
            pk.h[0] = __floats2half2_rn(pre[p].x, pre[p].y);
            pk.h[1] = __floats2half2_rn(pre[p].z, pre[p].w);
            *(uint2*)&stg[(p * 4 + lrow) * 40 + lc4 * 4] = pk.u;
        }
        __syncwarp();
        if (s < 7) {
#pragma unroll
            for (int p = 0; p < 8; ++p)
                pre[p] = ldcs4(&ab[(size_t)(mb + p * 4 + lrow) * 64 +
                                   (s + 1) * 8 + lc4]);
        }
#pragma unroll
        for (int ks = 0; ks < 2; ++ks) {
            uint32_t a0[2][4];
#pragma unroll
            for (int mt = 0; mt < 2; ++mt)
                ldsm_x4(smem_u32(&stg[(mt * 16 + row16) * 40 + ks * 16 + half8]),
                        a0[mt][0], a0[mt][1], a0[mt][2], a0[mt][3]);
            const int krow = s * 32 + ks * 16 + row16;
#pragma unroll
            for (int j = 0; j < 4; ++j) {
                uint32_t b0, b1r, b2r, b3r;
                ldsm_x4t(smem_u32(&Vh[krow * 72 + j * 16 + half8]),
                         b0, b1r, b2r, b3r);
#pragma unroll
                for (int mt = 0; mt < 2; ++mt) {
                    mma16816(accT[mt][2 * j],     a0[mt][0], a0[mt][1],
                             a0[mt][2], a0[mt][3], b0, b1r);
                    mma16816(accT[mt][2 * j + 1], a0[mt][0], a0[mt][1],
                             a0[mt][2], a0[mt][3], b2r, b3r);
                }
            }
        }
        __syncwarp();
    }

    // ------- stage Thi (32 rows x 64 cols fp16, stride 72) ---------------------
    {
        const int rloc = lane >> 2;
        const int c0   = (lane & 3) * 2;
#pragma unroll
        for (int mt = 0; mt < 2; ++mt)
#pragma unroll
            for (int q = 0; q < 8; ++q) {
                const int c = q * 8 + c0;
                *(half2*)&stg[(mt * 16 + rloc) * 72 + c] = __halves2half2(
                    __float2half_rn(accT[mt][q][0]), __float2half_rn(accT[mt][q][1]));
                *(half2*)&stg[(mt * 16 + rloc + 8) * 72 + c] = __halves2half2(
                    __float2half_rn(accT[mt][q][2]), __float2half_rn(accT[mt][q][3]));
            }
        __syncwarp();
    }

    // ------- Phase C: x = relu(Vh@Wroot + Thi@Wrel + b1), n-halved -------------
    {
        const int rloc = lane >> 2;
        const int c0   = (lane & 3) * 2;
        float part[2][8];   // [half][2 cols x 4 octets]
#pragma unroll
        for (int h = 0; h < 2; ++h) {
            float accX[2][4][4];
#pragma unroll
            for (int mt = 0; mt < 2; ++mt)
#pragma unroll
                for (int q = 0; q < 4; ++q)
#pragma unroll
                    for (int t = 0; t < 4; ++t) accX[mt][q][t] = 0.0f;

            // two terms: src=0 root (A=Vh, B cols 64+), src=1 rel (A=Thi, B cols 0+)
#pragma unroll
            for (int src = 0; src < 2; ++src) {
#pragma unroll
                for (int ks = 0; ks < 4; ++ks) {
                    uint32_t a0[2][4];
#pragma unroll
                    for (int mt = 0; mt < 2; ++mt) {
                        uint32_t addr = src == 0
                            ? smem_u32(&Vh[(mb + mt * 16 + row16) * 72 +
                                           ks * 16 + half8])
                            : smem_u32(&stg[(mt * 16 + row16) * 72 +
                                            ks * 16 + half8]);
                        ldsm_x4(addr, a0[mt][0], a0[mt][1], a0[mt][2], a0[mt][3]);
                    }
                    const int bcol = (src == 0 ? 64 : 0) + h * 32;
#pragma unroll
                    for (int j = 0; j < 2; ++j) {
                        uint32_t b0, b1r, b2r, b3r;
                        ldsm_x4t(smem_u32(&Whi[(ks * 16 + row16) * 136 +
                                               bcol + j * 16 + half8]),
                                 b0, b1r, b2r, b3r);
#pragma unroll
                        for (int mt = 0; mt < 2; ++mt) {
                            mma16816(accX[mt][2 * j],     a0[mt][0], a0[mt][1],
                                     a0[mt][2], a0[mt][3], b0, b1r);
                            mma16816(accX[mt][2 * j + 1], a0[mt][0], a0[mt][1],
                                     a0[mt][2], a0[mt][3], b2r, b3r);
                        }
                    }
                }
            }

            // epilogue for this n-half: relu + node-0 fold
#pragma unroll
            for (int t = 0; t < 8; ++t) part[h][t] = 0.0f;
#pragma unroll
            for (int mt = 0; mt < 2; ++mt) {
                const int row = mb + mt * 16 + rloc;
                const float a0lo = A0s[row];
                const float a0hi = A0s[row + 8];
#pragma unroll
                for (int q = 0; q < 4; ++q) {
                    const int c = h * 32 + q * 8 + c0;
                    float2 bb = *(float2*)&B1s[c];
                    float x00 = fmaxf(accX[mt][q][0] + bb.x, 0.0f);
                    float x01 = fmaxf(accX[mt][q][1] + bb.y, 0.0f);
                    float x80 = fmaxf(accX[mt][q][2] + bb.x, 0.0f);
                    float x81 = fmaxf(accX[mt][q][3] + bb.y, 0.0f);
                    part[h][2 * q]     += a0lo * x00 + a0hi * x80;
                    part[h][2 * q + 1] += a0lo * x01 + a0hi * x81;
                    if (wid == 0 && mt == 0 && rloc == 0) {  // x row 0
                        X0s[c]     = x00;
                        X0s[c + 1] = x01;
                    }
                }
            }
        }
        // reduce over the 8 row-groups (lanes differing in bits 2..4)
#pragma unroll
        for (int off = 4; off <= 16; off <<= 1)
#pragma unroll
            for (int h = 0; h < 2; ++h)
#pragma unroll
                for (int t = 0; t < 8; ++t)
                    part[h][t] += __shfl_xor_sync(0xffffffffu, part[h][t], off);
        if (lane < 4) {
#pragma unroll
            for (int h = 0; h < 2; ++h)
#pragma unroll
                for (int q = 0; q < 4; ++q) {
                    PART[wid * 64 + h * 32 + q * 8 + c0]     = part[h][2 * q];
                    PART[wid * 64 + h * 32 + q * 8 + c0 + 1] = part[h][2 * q + 1];
                }
        }
    }
    __syncthreads();

    // ---------------- Final head: layer 2 at node 0 + linear head --------------
    if (tid < 64) {
        float s = 0.0f;
#pragma unroll
        for (int w = 0; w < 8; ++w) s += PART[w * 64 + tid];
        SAs[tid] = s;   // SA = adj[0,:] @ x
    }
    __syncthreads();
    if (tid < 64) {
        float acc = b2[tid];
#pragma unroll 8
        for (int d = 0; d < 64; ++d)
            acc += SAs[d] * w2_rel[d * 64 + tid] + X0s[d] * w2_root[d * 64 + tid];
        float y = fmaxf(acc, 0.0f);
        SBs[tid] = y + X0s[tid];  // x0 + y0
    }
    __syncthreads();
    if (tid < 2) {
        float s = bf[tid];
#pragma unroll 16
        for (int d = 0; d < 64; ++d) s = fmaf(SBs[d], wf[d * 2 + tid], s);
        out[(size_t)b * 2 + tid] = s;
    }
}

extern "C" void kernel_launch(void* const* d_in, const int* in_sizes, int n_in,
                              void* d_out, int out_size) {
    const float* adj     = (const float*)d_in[0];
    const float* vec     = (const float*)d_in[1];
    const float* w1_rel  = (const float*)d_in[2];
    const float* w1_root = (const float*)d_in[3];
    const float* b1      = (const float*)d_in[4];
    const float* w2_rel  = (const float*)d_in[5];
    const float* w2_root = (const float*)d_in[6];
    const float* b2      = (const float*)d_in[7];
    const float* wf      = (const float*)d_in[8];
    const float* bf      = (const float*)d_in[9];
    float* out = (float*)d_out;

    cudaFuncSetAttribute(gnn_fused_kernel,
                         cudaFuncAttributeMaxDynamicSharedMemorySize, SMEM_BYTES);
    gnn_fused_kernel<<<NB, 256, SMEM_BYTES>>>(
        adj, vec, w1_rel, w1_root, b1, w2_rel, w2_root, b2, wf, bf, out);
}